// round 7
// baseline (speedup 1.0000x reference)
#include <cuda_runtime.h>
#include <cuda_bf16.h>
#include <stdint.h>

#define HD 256
#define NB 16
#define NFQ 1024
#define NGK 2048

typedef __nv_bfloat16 bf16;

// ---------------- scratch (device globals; no allocation allowed) ----------
static __device__ float g_x[NB * NFQ * HD];               // residual x (fp32)
static __device__ float g_s[(size_t)NB * NFQ * NGK];      // scores fp32 134MB
static __device__ float g_a[NB * NFQ * HD];               // attn out fp32
static __device__ bf16  g_xh[NB * NFQ * HD], g_xl[NB * NFQ * HD];
static __device__ bf16  g_hh[NB * NFQ * HD], g_hl[NB * NFQ * HD];   // history split
static __device__ bf16  g_gh[NB * NGK * HD], g_gl[NB * NGK * HD];   // graph split
static __device__ bf16  g_qh[NB * NFQ * HD], g_ql[NB * NFQ * HD];
static __device__ bf16  g_kh[NB * NGK * HD], g_kl[NB * NGK * HD];
static __device__ bf16  g_vh[NB * NGK * HD], g_vl[NB * NGK * HD];   // V^T [B][H][Nk]
static __device__ bf16  g_sh[(size_t)NB * NFQ * NGK];     // softmax weights hi
static __device__ bf16  g_sl[(size_t)NB * NFQ * NGK];     // softmax weights lo
static __device__ bf16  g_wth[12 * HD * HD], g_wtl[12 * HD * HD];   // W^T split
static __device__ float g_beff[12 * HD];
static __device__ float g_wtmp[12 * HD * HD];
static __device__ uint32_t g_mbhf[NB * NFQ * (NFQ / 32)]; // packed mask_hf
static __device__ uint32_t g_mbfg[NB * NFQ * (NGK / 32)]; // packed mask_fg

// =================== helpers =================================================
__device__ __forceinline__ uint32_t smem_u32(const void* p) {
    uint32_t a;
    asm("{ .reg .u64 t; cvta.to.shared.u64 t, %1; cvt.u32.u64 %0, t; }" : "=r"(a) : "l"(p));
    return a;
}
// 64-byte-row swizzle (bits[5:4] ^= bits[8:7])
#define SWZ(o) ((o) ^ (((o) >> 3) & 0x30))

__device__ __forceinline__ void bsplit(float x, float y, uint32_t& h, uint32_t& l) {
    __nv_bfloat162 hh = __floats2bfloat162_rn(x, y);
    float2 back = __bfloat1622float2(hh);
    __nv_bfloat162 ll = __floats2bfloat162_rn(x - back.x, y - back.y);
    h = *reinterpret_cast<uint32_t*>(&hh);
    l = *reinterpret_cast<uint32_t*>(&ll);
}
__device__ __forceinline__ void ldsm4(uint32_t addr, uint32_t& r0, uint32_t& r1,
                                      uint32_t& r2, uint32_t& r3) {
    asm volatile("ldmatrix.sync.aligned.m8n8.x4.shared.b16 {%0,%1,%2,%3}, [%4];"
                 : "=r"(r0), "=r"(r1), "=r"(r2), "=r"(r3) : "r"(addr));
}
__device__ __forceinline__ void mma16816(float* c, const uint32_t* a,
                                         uint32_t b0, uint32_t b1) {
    asm volatile(
        "mma.sync.aligned.m16n8k16.row.col.f32.bf16.bf16.f32 "
        "{%0,%1,%2,%3}, {%4,%5,%6,%7}, {%8,%9}, {%0,%1,%2,%3};"
        : "+f"(c[0]), "+f"(c[1]), "+f"(c[2]), "+f"(c[3])
        : "r"(a[0]), "r"(a[1]), "r"(a[2]), "r"(a[3]), "r"(b0), "r"(b1));
}
__device__ __forceinline__ uint32_t swaddr64(uint32_t base, int row, int unit) {
    uint32_t b = (uint32_t)(row * 64 + unit * 16);
    return base + SWZ(b);
}
__device__ __forceinline__ void cpa(uint32_t s, const bf16* g) {
    asm volatile("cp.async.cg.shared.global [%0], [%1], 16;"
                 :: "r"(s), "l"((uint64_t)__cvta_generic_to_global(g)) : "memory");
}

// smem per stage: Ah 8KB, Al 8KB, Bh 8KB, Bl 8KB = 32KB; 3 stages = 96KB
#define OFF_AH 0u
#define OFF_AL 8192u
#define OFF_BH 16384u
#define OFF_BL 24576u
#define STAGE  32768u
#define SMEM_BYTES (3 * 32768)

// =================== bf16x3 tensor-core GEMM ================================
// D[M,N] = alpha*(Ah+Al)@(Bh+Bl)^T + bias. A [M][K], B [N][K] bf16 K-major.
// CTA tile 128x128, K-chunk 32, 3-stage cp.async.
// Output modes: mbits -> masked fp32 (QK); Cf -> fp32; else bf16 hi/lo
// (transLd==0 row-major; transLd=R -> C[b*N*R + n*R + r], b=m/R, r=m%R).
__global__ __launch_bounds__(256, 2) void gemm_bf3(
    const bf16* __restrict__ Ah, const bf16* __restrict__ Al,
    const bf16* __restrict__ Bh, const bf16* __restrict__ Bl,
    const float* __restrict__ bias, const uint32_t* __restrict__ mbits,
    float* __restrict__ Cf, bf16* __restrict__ Ch, bf16* __restrict__ Cl,
    int N, int K, float alpha,
    long batchA, long batchB, long batchC, long batchMask, int mwords,
    int transLd)
{
    extern __shared__ char smem[];
    const uint32_t sb = smem_u32(smem);
    const int tid = threadIdx.x;
    const int wid = tid >> 5;
    const int lane = tid & 31;
    const int m0 = blockIdx.y * 128;
    const int n0 = blockIdx.x * 128;
    Ah += (long)blockIdx.z * batchA;
    Al += (long)blockIdx.z * batchA;
    Bh += (long)blockIdx.z * batchB;
    Bl += (long)blockIdx.z * batchB;

    const int wm = wid & 3;        // rows wm*32
    const int wn = wid >> 2;       // cols wn*64

    float acc[2][8][4];
#pragma unroll
    for (int i = 0; i < 2; i++)
#pragma unroll
        for (int j = 0; j < 8; j++)
#pragma unroll
            for (int r = 0; r < 4; r++) acc[i][j][r] = 0.f;

    const int lmat = lane >> 3, lr8 = lane & 7;
    const int aRowOff = (lmat & 1) * 8 + lr8;
    const int aUnitOff = lmat >> 1;
    const int bRowOff = (lmat >> 1) * 8 + lr8;
    const int bUnitOff = lmat & 1;

    const int nCh = K >> 5;

    auto issue = [&](int c) {
        const int k0 = c << 5;
        const uint32_t st = sb + (uint32_t)(c % 3) * STAGE;
#pragma unroll
        for (int i = 0; i < 2; ++i) {
            const int idx = tid + (i << 8);      // 0..511
            const int row = idx >> 2, un = idx & 3;
            const uint32_t so = SWZ((uint32_t)(row * 64 + un * 16));
            const long goA = (long)(m0 + row) * K + k0 + un * 8;
            cpa(st + OFF_AH + so, Ah + goA);
            cpa(st + OFF_AL + so, Al + goA);
            const long goB = (long)(n0 + row) * K + k0 + un * 8;
            cpa(st + OFF_BH + so, Bh + goB);
            cpa(st + OFF_BL + so, Bl + goB);
        }
        asm volatile("cp.async.commit_group;" ::: "memory");
    };

    issue(0);
    if (nCh > 1) issue(1);
    for (int c = 0; c < nCh; ++c) {
        if (c + 2 < nCh) {
            issue(c + 2);
            asm volatile("cp.async.wait_group 2;" ::: "memory");
        } else if (c + 1 < nCh) {
            asm volatile("cp.async.wait_group 1;" ::: "memory");
        } else {
            asm volatile("cp.async.wait_group 0;" ::: "memory");
        }
        __syncthreads();
        const uint32_t st = sb + (uint32_t)(c % 3) * STAGE;
#pragma unroll
        for (int ks = 0; ks < 2; ++ks) {
            uint32_t av[2][4], alv[2][4], bv[4][4];
            // A-hi
#pragma unroll
            for (int mi = 0; mi < 2; ++mi)
                ldsm4(swaddr64(st + OFF_AH, wm * 32 + mi * 16 + aRowOff,
                               ks * 2 + aUnitOff),
                      av[mi][0], av[mi][1], av[mi][2], av[mi][3]);
            // B-hi
#pragma unroll
            for (int g = 0; g < 4; ++g)
                ldsm4(swaddr64(st + OFF_BH, wn * 64 + g * 16 + bRowOff,
                               ks * 2 + bUnitOff),
                      bv[g][0], bv[g][1], bv[g][2], bv[g][3]);
            // P1: ah*bh
#pragma unroll
            for (int mi = 0; mi < 2; ++mi)
#pragma unroll
                for (int nj = 0; nj < 8; ++nj) {
                    const int g = nj >> 1, p = (nj & 1) * 2;
                    mma16816(acc[mi][nj], av[mi], bv[g][p], bv[g][p + 1]);
                }
            // A-lo
#pragma unroll
            for (int mi = 0; mi < 2; ++mi)
                ldsm4(swaddr64(st + OFF_AL, wm * 32 + mi * 16 + aRowOff,
                               ks * 2 + aUnitOff),
                      alv[mi][0], alv[mi][1], alv[mi][2], alv[mi][3]);
            // P2: al*bh
#pragma unroll
            for (int mi = 0; mi < 2; ++mi)
#pragma unroll
                for (int nj = 0; nj < 8; ++nj) {
                    const int g = nj >> 1, p = (nj & 1) * 2;
                    mma16816(acc[mi][nj], alv[mi], bv[g][p], bv[g][p + 1]);
                }
            // B-lo (reuse bv)
#pragma unroll
            for (int g = 0; g < 4; ++g)
                ldsm4(swaddr64(st + OFF_BL, wn * 64 + g * 16 + bRowOff,
                               ks * 2 + bUnitOff),
                      bv[g][0], bv[g][1], bv[g][2], bv[g][3]);
            // P3: ah*bl
#pragma unroll
            for (int mi = 0; mi < 2; ++mi)
#pragma unroll
                for (int nj = 0; nj < 8; ++nj) {
                    const int g = nj >> 1, p = (nj & 1) * 2;
                    mma16816(acc[mi][nj], av[mi], bv[g][p], bv[g][p + 1]);
                }
        }
        __syncthreads();
    }

    // ---- epilogue ----
    const int qrow = lane >> 2;
    const int qcol = (lane & 3) * 2;
#pragma unroll
    for (int mi = 0; mi < 2; ++mi) {
#pragma unroll
        for (int nj = 0; nj < 8; ++nj) {
            const int col = n0 + wn * 64 + nj * 8 + qcol;
            const int r0 = m0 + wm * 32 + mi * 16 + qrow;
            const int r1 = r0 + 8;
            float c0 = acc[mi][nj][0] * alpha;
            float c1 = acc[mi][nj][1] * alpha;
            float c2 = acc[mi][nj][2] * alpha;
            float c3 = acc[mi][nj][3] * alpha;
            if (bias) {
                float b0 = bias[col], b1 = bias[col + 1];
                c0 += b0; c1 += b1; c2 += b0; c3 += b1;
            }
            if (mbits) {
                // masked fp32 scores
                const uint32_t* mb = mbits + (long)blockIdx.z * batchMask;
                float* base = Cf + (long)blockIdx.z * batchC;
                uint32_t w0 = mb[(long)r0 * mwords + (col >> 5)];
                uint32_t w1 = mb[(long)r1 * mwords + (col >> 5)];
                const int b = col & 31;
                c0 = (w0 >> b) & 1 ? -1e12f : c0;
                c1 = (w0 >> (b + 1)) & 1 ? -1e12f : c1;
                c2 = (w1 >> b) & 1 ? -1e12f : c2;
                c3 = (w1 >> (b + 1)) & 1 ? -1e12f : c3;
                float2 p0 = {c0, c1};
                float2 p1 = {c2, c3};
                *reinterpret_cast<float2*>(base + (long)r0 * N + col) = p0;
                *reinterpret_cast<float2*>(base + (long)r1 * N + col) = p1;
            } else if (Cf) {
                float* base = Cf + (long)blockIdx.z * batchC;
                float2 p0 = {c0, c1};
                float2 p1 = {c2, c3};
                *reinterpret_cast<float2*>(base + (long)r0 * N + col) = p0;
                *reinterpret_cast<float2*>(base + (long)r1 * N + col) = p1;
            } else if (transLd == 0) {
                uint32_t h, l;
                bsplit(c0, c1, h, l);
                const long o0 = ((long)r0 * N + col) >> 1;
                reinterpret_cast<uint32_t*>(Ch)[o0] = h;
                reinterpret_cast<uint32_t*>(Cl)[o0] = l;
                bsplit(c2, c3, h, l);
                const long o1 = ((long)r1 * N + col) >> 1;
                reinterpret_cast<uint32_t*>(Ch)[o1] = h;
                reinterpret_cast<uint32_t*>(Cl)[o1] = l;
            } else {
                const int R = transLd;
                const int b0i = r0 / R, rr0 = r0 - b0i * R;
                const int b1i = r1 / R, rr1 = r1 - b1i * R;
                const long base0 = (long)b0i * N * R + rr0;
                const long base1 = (long)b1i * N * R + rr1;
                float vals[4] = {c0, c1, c2, c3};
                long offs[4] = {base0 + (long)col * R, base0 + (long)(col + 1) * R,
                                base1 + (long)col * R, base1 + (long)(col + 1) * R};
#pragma unroll
                for (int t = 0; t < 4; ++t) {
                    bf16 h = __float2bfloat16(vals[t]);
                    bf16 lo = __float2bfloat16(vals[t] - __bfloat162float(h));
                    Ch[offs[t]] = h;
                    Cl[offs[t]] = lo;
                }
            }
        }
    }
}

// =================== mask packing (int32 -> bits) ===========================
__global__ __launch_bounds__(256) void pack_mask(
    const int* __restrict__ m, uint32_t* __restrict__ bits, long nWords)
{
    const long w = (long)blockIdx.x * 8 + (threadIdx.x >> 5);
    const int lane = threadIdx.x & 31;
    if (w < nWords) {
        int v = m[w * 32 + lane];
        uint32_t b = __ballot_sync(0xffffffffu, v != 0);
        if (lane == 0) bits[w] = b;
    }
}

// =================== weight collapse ========================================
__global__ __launch_bounds__(256) void wstage(
    const float* __restrict__ Wq, const float* __restrict__ Wk,
    const float* __restrict__ Wv,
    float* __restrict__ wtmp, bf16* __restrict__ wth, bf16* __restrict__ wtl,
    int stage)
{
    __shared__ __align__(16) float As[16][64];
    __shared__ __align__(16) float Bs[16][64];
    const int z = blockIdx.z, t = z >> 2, l = z & 3;
    const float* Wsel = (t == 0 ? Wq : (t == 1 ? Wk : Wv)) + (size_t)l * 3 * HD * HD;
    const float* A;
    const float* B;
    if (stage == 0) { A = Wsel; B = Wsel + HD * HD; }
    else            { A = wtmp + (size_t)z * HD * HD; B = Wsel + 2 * HD * HD; }

    const int tid = threadIdx.x;
    const int tx = tid & 15, ty = tid >> 4;
    const int m0 = blockIdx.y * 64, n0 = blockIdx.x * 64;
    float acc[4][4] = {};
    const int a_row = tid >> 2, a_cg = tid & 3;
    const int b_row = tid >> 4, b_cg = tid & 15;
    for (int k0 = 0; k0 < HD; k0 += 16) {
        float4 av = *reinterpret_cast<const float4*>(A + (m0 + a_row) * HD + k0 + a_cg * 4);
        As[a_cg * 4 + 0][a_row] = av.x;
        As[a_cg * 4 + 1][a_row] = av.y;
        As[a_cg * 4 + 2][a_row] = av.z;
        As[a_cg * 4 + 3][a_row] = av.w;
        float4 bv = *reinterpret_cast<const float4*>(B + (k0 + b_row) * HD + n0 + b_cg * 4);
        *reinterpret_cast<float4*>(&Bs[b_row][b_cg * 4]) = bv;
        __syncthreads();
#pragma unroll
        for (int kk = 0; kk < 16; kk++) {
            float4 a = *reinterpret_cast<const float4*>(&As[kk][ty << 2]);
            float4 b = *reinterpret_cast<const float4*>(&Bs[kk][tx << 2]);
            float ar[4] = {a.x, a.y, a.z, a.w};
            float br[4] = {b.x, b.y, b.z, b.w};
#pragma unroll
            for (int i = 0; i < 4; i++)
#pragma unroll
                for (int j = 0; j < 4; j++) acc[i][j] = fmaf(ar[i], br[j], acc[i][j]);
        }
        __syncthreads();
    }
    if (stage == 0) {
        float* Cc = wtmp + (size_t)z * HD * HD;
#pragma unroll
        for (int i = 0; i < 4; i++) {
            float4 o = {acc[i][0], acc[i][1], acc[i][2], acc[i][3]};
            *reinterpret_cast<float4*>(Cc + (m0 + ty * 4 + i) * HD + n0 + tx * 4) = o;
        }
    } else {
        bf16* Ch = wth + (size_t)z * HD * HD;
        bf16* Cl = wtl + (size_t)z * HD * HD;
#pragma unroll
        for (int i = 0; i < 4; i++)
#pragma unroll
            for (int j = 0; j < 4; j++) {
                const int n = n0 + tx * 4 + j, k = m0 + ty * 4 + i;
                float v = acc[i][j];
                bf16 h = __float2bfloat16(v);
                bf16 lo = __float2bfloat16(v - __bfloat162float(h));
                Ch[(size_t)n * HD + k] = h;
                Cl[(size_t)n * HD + k] = lo;
            }
    }
}

// ---------------- bias collapse: beff = (b0@W1 + b1)@W2 + b2 ---------------
__global__ __launch_bounds__(256) void bias_collapse(
    const float* __restrict__ bq, const float* __restrict__ bk,
    const float* __restrict__ bv,
    const float* __restrict__ Wq, const float* __restrict__ Wk,
    const float* __restrict__ Wv,
    float* __restrict__ beff)
{
    const int t = blockIdx.x >> 2;
    const int l = blockIdx.x & 3;
    const float* bb = (t == 0 ? bq : (t == 1 ? bk : bv)) + (size_t)l * 3 * HD;
    const float* WW = (t == 0 ? Wq : (t == 1 ? Wk : Wv)) + (size_t)l * 3 * HD * HD;
    const int n = threadIdx.x;
    __shared__ float tmp[HD];

    float s = bb[HD + n];
    for (int k = 0; k < HD; k++)
        s = fmaf(bb[k], WW[HD * HD + k * HD + n], s);
    tmp[n] = s;
    __syncthreads();
    float s2 = bb[2 * HD + n];
    for (int k = 0; k < HD; k++)
        s2 = fmaf(tmp[k], WW[2 * HD * HD + k * HD + n], s2);
    beff[(size_t)blockIdx.x * HD + n] = s2;
}

// ---------------- fp32 -> bf16 hi/lo split ----------------------------------
__global__ __launch_bounds__(256) void split_kernel(
    const float* __restrict__ src, bf16* __restrict__ h, bf16* __restrict__ l,
    int n2)
{
    const int i = blockIdx.x * 256 + threadIdx.x;
    if (i < n2) {
        float2 f = reinterpret_cast<const float2*>(src)[i];
        uint32_t hh, ll;
        bsplit(f.x, f.y, hh, ll);
        reinterpret_cast<uint32_t*>(h)[i] = hh;
        reinterpret_cast<uint32_t*>(l)[i] = ll;
    }
}

// ---------------- softmax (scores pre-masked to -1e12) -> bf16 hi/lo --------
__global__ __launch_bounds__(256) void softmax_kernel(
    const float* __restrict__ S, bf16* __restrict__ Sh, bf16* __restrict__ Sl,
    int Nk)
{
    const long row = blockIdx.x;
    const float2* s2 = reinterpret_cast<const float2*>(S + row * (long)Nk);
    const int tid = threadIdx.x;
    const int nIter = Nk >> 9;  // 2 or 4

    float2 v[4];
    float vmax = -3.0e38f;
#pragma unroll 4
    for (int it = 0; it < nIter; it++) {
        float2 sv = s2[it * 256 + tid];
        v[it] = sv;
        vmax = fmaxf(vmax, fmaxf(sv.x, sv.y));
    }
    __shared__ float red[8];
#pragma unroll
    for (int o = 16; o > 0; o >>= 1)
        vmax = fmaxf(vmax, __shfl_xor_sync(0xffffffffu, vmax, o));
    if ((tid & 31) == 0) red[tid >> 5] = vmax;
    __syncthreads();
    if (tid == 0) {
        float t = red[0];
#pragma unroll
        for (int i = 1; i < 8; i++) t = fmaxf(t, red[i]);
        red[0] = t;
    }
    __syncthreads();
    vmax = red[0];
    __syncthreads();

    float sum = 0.f;
#pragma unroll 4
    for (int it = 0; it < nIter; it++) {
        float ex = __expf(v[it].x - vmax);
        float ey = __expf(v[it].y - vmax);
        v[it].x = ex; v[it].y = ey;
        sum += ex + ey;
    }
#pragma unroll
    for (int o = 16; o > 0; o >>= 1)
        sum += __shfl_xor_sync(0xffffffffu, sum, o);
    if ((tid & 31) == 0) red[tid >> 5] = sum;
    __syncthreads();
    if (tid == 0) {
        float t = 0.f;
#pragma unroll
        for (int i = 0; i < 8; i++) t += red[i];
        red[0] = t;
    }
    __syncthreads();
    const float inv = 1.f / red[0];

    uint32_t* oh = reinterpret_cast<uint32_t*>(Sh) + row * (Nk >> 1);
    uint32_t* ol = reinterpret_cast<uint32_t*>(Sl) + row * (Nk >> 1);
#pragma unroll 4
    for (int it = 0; it < nIter; it++) {
        uint32_t hh, ll;
        bsplit(v[it].x * inv, v[it].y * inv, hh, ll);
        oh[it * 256 + tid] = hh;
        ol[it * 256 + tid] = ll;
    }
}

// ---------------- layernorm + residual; emits split x -----------------------
__global__ __launch_bounds__(256) void ln_res_kernel(
    const float* __restrict__ attn, float* __restrict__ x,
    bf16* __restrict__ xh, bf16* __restrict__ xl,
    const float* __restrict__ gamma, const float* __restrict__ beta)
{
    const int warp = threadIdx.x >> 5;
    const int lane = threadIdx.x & 31;
    const long row = (long)blockIdx.x * 8 + warp;
    const float* a = attn + row * HD;
    float* xr = x + row * HD;

    float v[8];
    {
        float4 v0 = *reinterpret_cast<const float4*>(a + lane * 8);
        float4 v1 = *reinterpret_cast<const float4*>(a + lane * 8 + 4);
        v[0] = v0.x; v[1] = v0.y; v[2] = v0.z; v[3] = v0.w;
        v[4] = v1.x; v[5] = v1.y; v[6] = v1.z; v[7] = v1.w;
    }
    float s = 0.f;
#pragma unroll
    for (int i = 0; i < 8; i++) s += v[i];
#pragma unroll
    for (int o = 16; o > 0; o >>= 1) s += __shfl_xor_sync(0xffffffffu, s, o);
    const float mu = s * (1.f / HD);

    float sq = 0.f;
#pragma unroll
    for (int i = 0; i < 8; i++) {
        float d = v[i] - mu;
        sq = fmaf(d, d, sq);
    }
#pragma unroll
    for (int o = 16; o > 0; o >>= 1) sq += __shfl_xor_sync(0xffffffffu, sq, o);
    const float r = rsqrtf(sq * (1.f / HD) + 1e-5f);

    float4 x0 = *reinterpret_cast<const float4*>(xr + lane * 8);
    float4 x1 = *reinterpret_cast<const float4*>(xr + lane * 8 + 4);
    float xin[8] = {x0.x, x0.y, x0.z, x0.w, x1.x, x1.y, x1.z, x1.w};

    float out[8];
#pragma unroll
    for (int i = 0; i < 8; i++) {
        const int col = lane * 8 + i;
        out[i] = (v[i] - mu) * r * gamma[col] + beta[col] + xin[i];
    }
    float4 o0 = {out[0], out[1], out[2], out[3]};
    float4 o1 = {out[4], out[5], out[6], out[7]};
    *reinterpret_cast<float4*>(xr + lane * 8) = o0;
    *reinterpret_cast<float4*>(xr + lane * 8 + 4) = o1;

    uint32_t* ph = reinterpret_cast<uint32_t*>(xh) + row * (HD >> 1) + lane * 4;
    uint32_t* pl = reinterpret_cast<uint32_t*>(xl) + row * (HD >> 1) + lane * 4;
#pragma unroll
    for (int i = 0; i < 4; i++) {
        uint32_t hh, ll;
        bsplit(out[2 * i], out[2 * i + 1], hh, ll);
        ph[i] = hh;
        pl[i] = ll;
    }
}

// ---------------- final: out = future + x ----------------------------------
__global__ __launch_bounds__(256) void final_add(
    const float* __restrict__ fut, const float* __restrict__ x,
    float* __restrict__ o, int n4)
{
    const int i = blockIdx.x * blockDim.x + threadIdx.x;
    if (i < n4) {
        float4 a = reinterpret_cast<const float4*>(fut)[i];
        float4 b = reinterpret_cast<const float4*>(x)[i];
        float4 c = {a.x + b.x, a.y + b.y, a.z + b.z, a.w + b.w};
        reinterpret_cast<float4*>(o)[i] = c;
    }
}

// ---------------------------------------------------------------------------
extern "C" void kernel_launch(void* const* d_in, const int* in_sizes, int n_in,
                              void* d_out, int out_size)
{
    const float* future  = (const float*)d_in[0];
    const float* history = (const float*)d_in[1];
    const float* graph   = (const float*)d_in[2];
    const int*   mask_hf = (const int*)d_in[3];
    const int*   mask_fg = (const int*)d_in[4];
    const float* Wq      = (const float*)d_in[5];
    const float* bq      = (const float*)d_in[6];
    const float* Wk      = (const float*)d_in[7];
    const float* bk      = (const float*)d_in[8];
    const float* Wv      = (const float*)d_in[9];
    const float* bv      = (const float*)d_in[10];
    const float* gamma   = (const float*)d_in[11];
    const float* beta    = (const float*)d_in[12];
    float* out = (float*)d_out;

    float *px, *ps, *pa, *pbeff, *pwtmp;
    bf16 *pxh, *pxl, *phh, *phl, *pgh, *pgl, *pqh, *pql, *pkh, *pkl;
    bf16 *pvh, *pvl, *psh, *psl, *pwth, *pwtl;
    uint32_t *pmbhf, *pmbfg;
    cudaGetSymbolAddress((void**)&px,    g_x);
    cudaGetSymbolAddress((void**)&ps,    g_s);
    cudaGetSymbolAddress((void**)&pa,    g_a);
    cudaGetSymbolAddress((void**)&pbeff, g_beff);
    cudaGetSymbolAddress((void**)&pwtmp, g_wtmp);
    cudaGetSymbolAddress((void**)&pxh,   g_xh);
    cudaGetSymbolAddress((void**)&pxl,   g_xl);
    cudaGetSymbolAddress((void**)&phh,   g_hh);
    cudaGetSymbolAddress((void**)&phl,   g_hl);
    cudaGetSymbolAddress((void**)&pgh,   g_gh);
    cudaGetSymbolAddress((void**)&pgl,   g_gl);
    cudaGetSymbolAddress((void**)&pqh,   g_qh);
    cudaGetSymbolAddress((void**)&pql,   g_ql);
    cudaGetSymbolAddress((void**)&pkh,   g_kh);
    cudaGetSymbolAddress((void**)&pkl,   g_kl);
    cudaGetSymbolAddress((void**)&pvh,   g_vh);
    cudaGetSymbolAddress((void**)&pvl,   g_vl);
    cudaGetSymbolAddress((void**)&psh,   g_sh);
    cudaGetSymbolAddress((void**)&psl,   g_sl);
    cudaGetSymbolAddress((void**)&pwth,  g_wth);
    cudaGetSymbolAddress((void**)&pwtl,  g_wtl);
    cudaGetSymbolAddress((void**)&pmbhf, g_mbhf);
    cudaGetSymbolAddress((void**)&pmbfg, g_mbfg);

    cudaFuncSetAttribute(gemm_bf3, cudaFuncAttributeMaxDynamicSharedMemorySize,
                         SMEM_BYTES);

    // ---- collapse stacked affine layers; pack masks -------------------------
    wstage<<<dim3(4, 4, 12), 256>>>(Wq, Wk, Wv, pwtmp, pwth, pwtl, 0);
    wstage<<<dim3(4, 4, 12), 256>>>(Wq, Wk, Wv, pwtmp, pwth, pwtl, 1);
    bias_collapse<<<12, 256>>>(bq, bk, bv, Wq, Wk, Wv, pbeff);
    {
        const long wHF = (long)NB * NFQ * (NFQ / 32);
        const long wFG = (long)NB * NFQ * (NGK / 32);
        pack_mask<<<(unsigned)(wHF / 8), 256>>>(mask_hf, pmbhf, wHF);
        pack_mask<<<(unsigned)(wFG / 8), 256>>>(mask_fg, pmbfg, wFG);
    }

    // ---- x = future; split inputs ------------------------------------------
    cudaMemcpyAsync(px, future, sizeof(float) * NB * NFQ * HD,
                    cudaMemcpyDeviceToDevice, 0);
    {
        const int n2f = NB * NFQ * HD / 2;
        const int n2g = NB * NGK * HD / 2;
        split_kernel<<<n2f / 256, 256>>>(future, pxh, pxl, n2f);
        split_kernel<<<n2f / 256, 256>>>(history, phh, phl, n2f);
        split_kernel<<<n2g / 256, 256>>>(graph, pgh, pgl, n2g);
    }

    // ---- 4 attention layers --------------------------------------------------
    for (int l = 0; l < 4; l++) {
        const bf16* x2h = (l < 2) ? phh : pgh;
        const bf16* x2l = (l < 2) ? phl : pgl;
        const int   Nk  = (l < 2) ? NFQ : NGK;
        const uint32_t* mb = (l < 2) ? pmbhf : pmbfg;

        const bf16* Wqh = pwth + (size_t)(0 * 4 + l) * HD * HD;
        const bf16* Wql = pwtl + (size_t)(0 * 4 + l) * HD * HD;
        const bf16* Wkh = pwth + (size_t)(1 * 4 + l) * HD * HD;
        const bf16* Wkl = pwtl + (size_t)(1 * 4 + l) * HD * HD;
        const bf16* Wvh = pwth + (size_t)(2 * 4 + l) * HD * HD;
        const bf16* Wvl = pwtl + (size_t)(2 * 4 + l) * HD * HD;
        const float* beq = pbeff + (size_t)(0 * 4 + l) * HD;
        const float* bek = pbeff + (size_t)(1 * 4 + l) * HD;
        const float* bev = pbeff + (size_t)(2 * 4 + l) * HD;

        // projections -> split bf16 outputs
        gemm_bf3<<<dim3(HD / 128, (NB * NFQ) / 128, 1), 256, SMEM_BYTES>>>(
            pxh, pxl, Wqh, Wql, beq, nullptr, nullptr, pqh, pql,
            HD, HD, 1.f, 0, 0, 0, 0, 0, 0);
        gemm_bf3<<<dim3(HD / 128, (NB * Nk) / 128, 1), 256, SMEM_BYTES>>>(
            x2h, x2l, Wkh, Wkl, bek, nullptr, nullptr, pkh, pkl,
            HD, HD, 1.f, 0, 0, 0, 0, 0, 0);
        gemm_bf3<<<dim3(HD / 128, (NB * Nk) / 128, 1), 256, SMEM_BYTES>>>(
            x2h, x2l, Wvh, Wvl, bev, nullptr, nullptr, pvh, pvl,
            HD, HD, 1.f, 0, 0, 0, 0, 0, Nk);

        // scores = mask(Q @ K^T / 16), batched over B, fp32 + -1e12 fill
        gemm_bf3<<<dim3(Nk / 128, NFQ / 128, NB), 256, SMEM_BYTES>>>(
            pqh, pql, pkh, pkl, nullptr, mb, ps, nullptr, nullptr,
            Nk, HD, 0.0625f,
            (long)NFQ * HD, (long)Nk * HD, (long)NFQ * Nk,
            (long)NFQ * (Nk / 32), Nk / 32, 0);

        // softmax -> split bf16 weights (masked lanes are exactly 0)
        softmax_kernel<<<NB * NFQ, 256>>>(ps, psh, psl, Nk);

        // attn = W @ V  (A = weights, B = V^T), batched over B
        gemm_bf3<<<dim3(HD / 128, NFQ / 128, NB), 256, SMEM_BYTES>>>(
            psh, psl, pvh, pvl, nullptr, nullptr, pa, nullptr, nullptr,
            HD, Nk, 1.f,
            (long)NFQ * Nk, (long)HD * Nk, (long)NFQ * HD, 0, 0, 0);

        // x = LN(attn)*gamma + beta + x; also emit split x
        ln_res_kernel<<<(NB * NFQ) / 8, 256>>>(pa, px, pxh, pxl,
                                               gamma + l * HD, beta + l * HD);
    }

    // ---- out = future + x ------------------------------------------------------
    const int n4 = NB * NFQ * HD / 4;
    final_add<<<(n4 + 255) / 256, 256>>>(future, px, out, n4);
}